// round 5
// baseline (speedup 1.0000x reference)
#include <cuda_runtime.h>
#include <cuda_bf16.h>

#define NUM_USERS 100000
#define NUM_ITEMS 200000
#define NN        (NUM_USERS + NUM_ITEMS)   // 300000
#define D         64
#define NNZ       5000000
#define BATCH     16384
#define WIDTH     64                         // ELL width
#define MAX_SPILL 4096
#define MAXB      (2 * BATCH)                // max unique batch nodes

// Full layer outputs for layers 1,2 (each 76.8 MB); layer 3 is compact (8.4 MB)
__device__ float g_A[(size_t)NN * D];
__device__ float g_B[(size_t)NN * D];
__device__ float g_C[(size_t)MAXB * D];

// ELL storage: packed (col, val_bits) per slot. 153.6 MB
__device__ int2 g_ell[(size_t)NN * WIDTH];
__device__ int  g_len[NN];

// Batch-node compaction
__device__ int g_slot[NN];      // -1, then 1 = marked, then compact slot id
__device__ int g_blist[MAXB];
__device__ int g_bcount;

// Spill safety net (degree > WIDTH; expected empty for this dataset)
__device__ int   g_spill_count;
__device__ int   g_srow[MAX_SPILL];
__device__ int   g_scol[MAX_SPILL];
__device__ float g_sval[MAX_SPILL];

// ---------------------------------------------------------------------------
__global__ void init_kernel() {
    int i = blockIdx.x * blockDim.x + threadIdx.x;
    if (i < NN) { g_len[i] = 0; g_slot[i] = -1; }
    if (i == 0) { g_spill_count = 0; g_bcount = 0; }
}

__global__ void ell_fill_kernel(const int*   __restrict__ erow,
                                const int*   __restrict__ ecol,
                                const float* __restrict__ evals) {
    int i = blockIdx.x * blockDim.x + threadIdx.x;
    if (i >= NNZ) return;
    int   row = erow[i];
    int   col = ecol[i];
    float val = evals[i];
    int pos = atomicAdd(&g_len[row], 1);
    if (pos < WIDTH) {
        g_ell[(size_t)row * WIDTH + pos] = make_int2(col, __float_as_int(val));
    } else {
        int s = atomicAdd(&g_spill_count, 1);
        if (s < MAX_SPILL) {
            g_srow[s] = row; g_scol[s] = col; g_sval[s] = val;
        }
    }
}

__global__ void mark_kernel(const int* __restrict__ users,
                            const int* __restrict__ items) {
    int i = blockIdx.x * blockDim.x + threadIdx.x;
    if (i < BATCH)                 g_slot[users[i]] = 1;
    else if (i < 2 * BATCH)        g_slot[NUM_USERS + items[i - BATCH]] = 1;
}

__global__ void compact_kernel() {
    int i = blockIdx.x * blockDim.x + threadIdx.x;
    if (i >= NN) return;
    if (g_slot[i] == 1) {
        int pos = atomicAdd(&g_bcount, 1);
        g_blist[pos] = i;
        g_slot[i] = pos;
    }
}

// ---------------------------------------------------------------------------
// stage 0: src = (uemb, iemb), dst = g_A ; stage 1: src = g_A, dst = g_B
__device__ __forceinline__ void stage_ptrs(int stage,
                                           const float* uemb, const float* iemb,
                                           const float*& su, const float*& si,
                                           float*& dst) {
    if (stage == 0) { su = uemb; si = iemb;                        dst = g_A; }
    else            { su = g_A;  si = g_A + (size_t)NUM_USERS * D; dst = g_B; }
}

// Warp computes one output row from its ELL entries into acc, then stores.
__device__ __forceinline__ void spmm_row(int node, int lane,
                                         const float* __restrict__ su,
                                         const float* __restrict__ si,
                                         float* __restrict__ daddr) {
    int len = min(g_len[node], WIDTH);
    const int2* erow = g_ell + (size_t)node * WIDTH;

    float2 acc = make_float2(0.f, 0.f);
    for (int base = 0; base < len; base += 32) {
        int n = min(32, len - base);
        int2 ev = make_int2(0, 0);
        if (base + lane < len)
            ev = erow[base + lane];
        for (int j = 0; j < n; j++) {
            int   cj = __shfl_sync(0xFFFFFFFFu, ev.x, j);
            float vj = __int_as_float(__shfl_sync(0xFFFFFFFFu, ev.y, j));
            const float* srow = (cj < NUM_USERS)
                              ? (su + (size_t)cj * D)
                              : (si + (size_t)(cj - NUM_USERS) * D);
            float2 x = *reinterpret_cast<const float2*>(srow + 2 * lane);
            acc.x += vj * x.x;
            acc.y += vj * x.y;
        }
    }
    *reinterpret_cast<float2*>(daddr + 2 * lane) = acc;
}

// Full SpMM (layers 1, 2): one warp per destination row.
__global__ void spmm_ell_kernel(const float* __restrict__ uemb,
                                const float* __restrict__ iemb,
                                int stage) {
    int warp = (blockIdx.x * blockDim.x + threadIdx.x) >> 5;
    int lane = threadIdx.x & 31;
    if (warp >= NN) return;
    const float* su; const float* si; float* dst;
    stage_ptrs(stage, uemb, iemb, su, si, dst);
    spmm_row(warp, lane, su, si, dst + (size_t)warp * D);
}

// Layer-3 SpMM restricted to batch nodes; compact store into g_C.
__global__ void spmm_batch_kernel() {
    int warp = (blockIdx.x * blockDim.x + threadIdx.x) >> 5;
    int lane = threadIdx.x & 31;
    if (warp >= g_bcount) return;
    int node = g_blist[warp];
    spmm_row(node, lane,
             g_B, g_B + (size_t)NUM_USERS * D,
             g_C + (size_t)warp * D);
}

// Spill mop-up (stages 0,1 full; stage 2 only for marked rows, into g_C).
__global__ void spill_kernel(const float* __restrict__ uemb,
                             const float* __restrict__ iemb,
                             int stage) {
    int cnt = min(g_spill_count, MAX_SPILL);
    int idx = blockIdx.x * blockDim.x + threadIdx.x;
    int e = idx >> 4;
    int q = idx & 15;
    if (e >= cnt) return;

    int   row = g_srow[e];
    int   col = g_scol[e];
    float v   = g_sval[e];

    const float* su; const float* si; float* daddr;
    if (stage < 2) {
        float* dst;
        stage_ptrs(stage, uemb, iemb, su, si, dst);
        daddr = dst + (size_t)row * D;
    } else {
        int slot = g_slot[row];
        if (slot < 0) return;                 // row not in batch: e3 not needed
        su = g_B; si = g_B + (size_t)NUM_USERS * D;
        daddr = g_C + (size_t)slot * D;
    }
    const float* srow = (col < NUM_USERS)
                      ? (su + (size_t)col * D)
                      : (si + (size_t)(col - NUM_USERS) * D);
    float4 x = *reinterpret_cast<const float4*>(srow + q * 4);
    float* p = daddr + q * 4;
    asm volatile("red.global.add.v4.f32 [%0], {%1, %2, %3, %4};"
                 :: "l"(p), "f"(v * x.x), "f"(v * x.y), "f"(v * x.z), "f"(v * x.w)
                 : "memory");
}

// ---------------------------------------------------------------------------
// gamma[b] = dot( (e0_u+e1_u+e2_u+e3_u)/4 , (e0_i+e1_i+e2_i+e3_i)/4 )
__global__ void final_kernel(const int*   __restrict__ users,
                             const int*   __restrict__ items,
                             const float* __restrict__ uemb,
                             const float* __restrict__ iemb,
                             float*       __restrict__ out) {
    int warp = (blockIdx.x * blockDim.x + threadIdx.x) >> 5;
    int lane = threadIdx.x & 31;
    if (warp >= BATCH) return;

    int u  = __ldg(users + warp);
    int it = __ldg(items + warp);
    int nu = u;
    int ni = NUM_USERS + it;

    size_t urow = (size_t)nu * D;
    size_t irow = (size_t)ni * D;
    size_t uc   = (size_t)g_slot[nu] * D;    // compact e3 row
    size_t ic   = (size_t)g_slot[ni] * D;

    float dot = 0.f;
#pragma unroll
    for (int k = 0; k < 2; k++) {
        int d = lane + k * 32;
        float uv = __ldg(uemb + (size_t)u * D + d)
                 + g_A[urow + d] + g_B[urow + d] + g_C[uc + d];
        float iv = __ldg(iemb + (size_t)it * D + d)
                 + g_A[irow + d] + g_B[irow + d] + g_C[ic + d];
        dot += uv * iv;
    }
#pragma unroll
    for (int off = 16; off > 0; off >>= 1)
        dot += __shfl_xor_sync(0xFFFFFFFFu, dot, off);

    if (lane == 0) out[warp] = dot * 0.0625f;   // (1/4)*(1/4)
}

// ---------------------------------------------------------------------------
extern "C" void kernel_launch(void* const* d_in, const int* in_sizes, int n_in,
                              void* d_out, int out_size) {
    const int*   users = (const int*)  d_in[0];
    const int*   items = (const int*)  d_in[1];
    const int*   erow  = (const int*)  d_in[2];
    const int*   ecol  = (const int*)  d_in[3];
    const float* evals = (const float*)d_in[4];
    const float* uemb  = (const float*)d_in[5];
    const float* iemb  = (const float*)d_in[6];
    float* out = (float*)d_out;

    // --- build ELL + batch-node compaction ---
    init_kernel<<<(NN + 255) / 256, 256>>>();
    ell_fill_kernel<<<(NNZ + 255) / 256, 256>>>(erow, ecol, evals);
    mark_kernel<<<(2 * BATCH + 255) / 256, 256>>>(users, items);
    compact_kernel<<<(NN + 255) / 256, 256>>>();

    int threads = 256;                         // 8 warps/block
    int blocks  = (NN + 7) / 8;                // 37500
    int bblocks = (MAXB + 7) / 8;              // 4096
    int sblocks = (MAX_SPILL * 16 + 255) / 256;

    // --- layers 1,2 full; layer 3 batch-restricted ---
    spmm_ell_kernel<<<blocks, threads>>>(uemb, iemb, 0);
    spill_kernel<<<sblocks, 256>>>(uemb, iemb, 0);

    spmm_ell_kernel<<<blocks, threads>>>(uemb, iemb, 1);
    spill_kernel<<<sblocks, 256>>>(uemb, iemb, 1);

    spmm_batch_kernel<<<bblocks, threads>>>();
    spill_kernel<<<sblocks, 256>>>(uemb, iemb, 2);

    // --- final gather + dot ---
    final_kernel<<<(BATCH + 7) / 8, 256>>>(users, items, uemb, iemb, out);
}

// round 6
// speedup vs baseline: 1.5520x; 1.5520x over previous
#include <cuda_runtime.h>
#include <cuda_bf16.h>

#define NUM_USERS 100000
#define NUM_ITEMS 200000
#define NN        (NUM_USERS + NUM_ITEMS)   // 300000
#define D         64
#define NNZ       5000000
#define BATCH     16384
#define WIDTH     32                         // ELL width (P(deg>32) ~ 5e-5, spill net)
#define MAX_SPILL 16384
#define MAXB      (2 * BATCH)                // max unique batch nodes

// Full layer outputs for layers 1,2 (each 76.8 MB); layer 3 compact (8.4 MB)
__device__ float g_A[(size_t)NN * D];
__device__ float g_B[(size_t)NN * D];
__device__ float g_C[(size_t)MAXB * D];

// ELL storage: packed (col, val_bits). 300000*32*8B = 76.8 MB (L2-resident)
__device__ int2 g_ell[(size_t)NN * WIDTH];
__device__ int  g_len[NN];

// Batch-node compaction
__device__ int g_slot[NN];
__device__ int g_blist[MAXB];
__device__ int g_bcount;

// Spill safety net (degree > WIDTH)
__device__ int   g_spill_count;
__device__ int   g_srow[MAX_SPILL];
__device__ int   g_scol[MAX_SPILL];
__device__ float g_sval[MAX_SPILL];

// ---------------------------------------------------------------------------
__global__ void init_kernel() {
    int i = blockIdx.x * blockDim.x + threadIdx.x;
    if (i < NN) { g_len[i] = 0; g_slot[i] = -1; }
    if (i == 0) { g_spill_count = 0; g_bcount = 0; }
}

__global__ void ell_fill_kernel(const int*   __restrict__ erow,
                                const int*   __restrict__ ecol,
                                const float* __restrict__ evals) {
    int i = blockIdx.x * blockDim.x + threadIdx.x;
    if (i >= NNZ) return;
    int   row = __ldg(erow + i);
    int   col = __ldg(ecol + i);
    float val = __ldg(evals + i);
    int pos = atomicAdd(&g_len[row], 1);
    if (pos < WIDTH) {
        g_ell[(size_t)row * WIDTH + pos] = make_int2(col, __float_as_int(val));
    } else {
        int s = atomicAdd(&g_spill_count, 1);
        if (s < MAX_SPILL) {
            g_srow[s] = row; g_scol[s] = col; g_sval[s] = val;
        }
    }
}

__global__ void mark_kernel(const int* __restrict__ users,
                            const int* __restrict__ items) {
    int i = blockIdx.x * blockDim.x + threadIdx.x;
    if (i < BATCH)            g_slot[users[i]] = 1;
    else if (i < 2 * BATCH)   g_slot[NUM_USERS + items[i - BATCH]] = 1;
}

__global__ void compact_kernel() {
    int i = blockIdx.x * blockDim.x + threadIdx.x;
    if (i >= NN) return;
    if (g_slot[i] == 1) {
        int pos = atomicAdd(&g_bcount, 1);
        g_blist[pos] = i;
        g_slot[i] = pos;
    }
}

// ---------------------------------------------------------------------------
// stage 0: src = (uemb, iemb), dst = g_A ; stage 1: src = g_A, dst = g_B
__device__ __forceinline__ void stage_ptrs(int stage,
                                           const float* uemb, const float* iemb,
                                           const float*& su, const float*& si,
                                           float*& dst) {
    if (stage == 0) { su = uemb; si = iemb;                        dst = g_A; }
    else            { su = g_A;  si = g_A + (size_t)NUM_USERS * D; dst = g_B; }
}

// Warp computes one output row (single ELL chunk, len <= 32).
// Padding iterations (j >= n) carry c=0, v=0: load row 0 (L1-hot), FMA adds 0.
__device__ __forceinline__ float2 spmm_row_acc(int node, int lane,
                                               const float* __restrict__ su,
                                               const float* __restrict__ si) {
    int n = min(g_len[node], WIDTH);
    int2 ev = make_int2(0, 0);
    if (lane < n)
        ev = __ldcs(g_ell + (size_t)node * WIDTH + lane);  // evict-first stream

    float2 acc = make_float2(0.f, 0.f);
    int n4 = (n + 3) & ~3;
    for (int j = 0; j < n4; j += 4) {
#pragma unroll
        for (int k = 0; k < 4; k++) {
            int   cj = __shfl_sync(0xFFFFFFFFu, ev.x, j + k);
            float vj = __int_as_float(__shfl_sync(0xFFFFFFFFu, ev.y, j + k));
            const float* srow = (cj < NUM_USERS)
                              ? (su + (size_t)cj * D)
                              : (si + (size_t)(cj - NUM_USERS) * D);
            float2 x = *reinterpret_cast<const float2*>(srow + 2 * lane);
            acc.x += vj * x.x;
            acc.y += vj * x.y;
        }
    }
    return acc;
}

// Full SpMM (layers 1, 2): one warp per destination row, streaming store.
__global__ void spmm_ell_kernel(const float* __restrict__ uemb,
                                const float* __restrict__ iemb,
                                int stage) {
    int warp = (blockIdx.x * blockDim.x + threadIdx.x) >> 5;
    int lane = threadIdx.x & 31;
    if (warp >= NN) return;
    const float* su; const float* si; float* dst;
    stage_ptrs(stage, uemb, iemb, su, si, dst);
    float2 acc = spmm_row_acc(warp, lane, su, si);
    __stcs(reinterpret_cast<float2*>(dst + (size_t)warp * D + 2 * lane), acc);
}

// Layer-3 SpMM restricted to batch nodes; compact store into g_C.
__global__ void spmm_batch_kernel() {
    int warp = (blockIdx.x * blockDim.x + threadIdx.x) >> 5;
    int lane = threadIdx.x & 31;
    if (warp >= g_bcount) return;
    int node = g_blist[warp];
    float2 acc = spmm_row_acc(node, lane, g_B, g_B + (size_t)NUM_USERS * D);
    *reinterpret_cast<float2*>(g_C + (size_t)warp * D + 2 * lane) = acc;
}

// Spill mop-up (stages 0,1 full; stage 2 only for marked rows, into g_C).
__global__ void spill_kernel(const float* __restrict__ uemb,
                             const float* __restrict__ iemb,
                             int stage) {
    int cnt = min(g_spill_count, MAX_SPILL);
    int idx = blockIdx.x * blockDim.x + threadIdx.x;
    int e = idx >> 4;
    int q = idx & 15;
    if (e >= cnt) return;

    int   row = g_srow[e];
    int   col = g_scol[e];
    float v   = g_sval[e];

    const float* su; const float* si; float* daddr;
    if (stage < 2) {
        float* dst;
        stage_ptrs(stage, uemb, iemb, su, si, dst);
        daddr = dst + (size_t)row * D;
    } else {
        int slot = g_slot[row];
        if (slot < 0) return;
        su = g_B; si = g_B + (size_t)NUM_USERS * D;
        daddr = g_C + (size_t)slot * D;
    }
    const float* srow = (col < NUM_USERS)
                      ? (su + (size_t)col * D)
                      : (si + (size_t)(col - NUM_USERS) * D);
    float4 x = *reinterpret_cast<const float4*>(srow + q * 4);
    float* p = daddr + q * 4;
    asm volatile("red.global.add.v4.f32 [%0], {%1, %2, %3, %4};"
                 :: "l"(p), "f"(v * x.x), "f"(v * x.y), "f"(v * x.z), "f"(v * x.w)
                 : "memory");
}

// ---------------------------------------------------------------------------
// gamma[b] = dot( (e0_u+e1_u+e2_u+e3_u)/4 , (e0_i+e1_i+e2_i+e3_i)/4 )
__global__ void final_kernel(const int*   __restrict__ users,
                             const int*   __restrict__ items,
                             const float* __restrict__ uemb,
                             const float* __restrict__ iemb,
                             float*       __restrict__ out) {
    int warp = (blockIdx.x * blockDim.x + threadIdx.x) >> 5;
    int lane = threadIdx.x & 31;
    if (warp >= BATCH) return;

    int u  = __ldg(users + warp);
    int it = __ldg(items + warp);
    int nu = u;
    int ni = NUM_USERS + it;

    size_t urow = (size_t)nu * D;
    size_t irow = (size_t)ni * D;
    size_t uc   = (size_t)g_slot[nu] * D;
    size_t ic   = (size_t)g_slot[ni] * D;

    float dot = 0.f;
#pragma unroll
    for (int k = 0; k < 2; k++) {
        int d = lane + k * 32;
        float uv = __ldg(uemb + (size_t)u * D + d)
                 + g_A[urow + d] + g_B[urow + d] + g_C[uc + d];
        float iv = __ldg(iemb + (size_t)it * D + d)
                 + g_A[irow + d] + g_B[irow + d] + g_C[ic + d];
        dot += uv * iv;
    }
#pragma unroll
    for (int off = 16; off > 0; off >>= 1)
        dot += __shfl_xor_sync(0xFFFFFFFFu, dot, off);

    if (lane == 0) out[warp] = dot * 0.0625f;   // (1/4)*(1/4)
}

// ---------------------------------------------------------------------------
extern "C" void kernel_launch(void* const* d_in, const int* in_sizes, int n_in,
                              void* d_out, int out_size) {
    const int*   users = (const int*)  d_in[0];
    const int*   items = (const int*)  d_in[1];
    const int*   erow  = (const int*)  d_in[2];
    const int*   ecol  = (const int*)  d_in[3];
    const float* evals = (const float*)d_in[4];
    const float* uemb  = (const float*)d_in[5];
    const float* iemb  = (const float*)d_in[6];
    float* out = (float*)d_out;

    // --- build ELL + batch-node compaction ---
    init_kernel<<<(NN + 255) / 256, 256>>>();
    ell_fill_kernel<<<(NNZ + 255) / 256, 256>>>(erow, ecol, evals);
    mark_kernel<<<(2 * BATCH + 255) / 256, 256>>>(users, items);
    compact_kernel<<<(NN + 255) / 256, 256>>>();

    int threads = 256;                         // 8 warps/block
    int blocks  = (NN + 7) / 8;                // 37500
    int bblocks = (MAXB + 7) / 8;              // 4096
    int sblocks = (MAX_SPILL * 16 + 255) / 256;

    // --- layers 1,2 full; layer 3 batch-restricted ---
    spmm_ell_kernel<<<blocks, threads>>>(uemb, iemb, 0);
    spill_kernel<<<sblocks, 256>>>(uemb, iemb, 0);

    spmm_ell_kernel<<<blocks, threads>>>(uemb, iemb, 1);
    spill_kernel<<<sblocks, 256>>>(uemb, iemb, 1);

    spmm_batch_kernel<<<bblocks, threads>>>();
    spill_kernel<<<sblocks, 256>>>(uemb, iemb, 2);

    // --- final gather + dot ---
    final_kernel<<<(BATCH + 7) / 8, 256>>>(users, items, uemb, iemb, out);
}

// round 7
// speedup vs baseline: 1.5867x; 1.0224x over previous
#include <cuda_runtime.h>
#include <cuda_bf16.h>

#define NUM_USERS 100000
#define NUM_ITEMS 200000
#define NN        (NUM_USERS + NUM_ITEMS)   // 300000
#define D         64
#define NNZ       5000000
#define BATCH     16384
#define WIDTH     32                         // ELL width (P(deg>32) ~ 5e-5, spill net)
#define MAX_SPILL 2048

// Full layer outputs for layers 1,2 (each 76.8 MB); layer 3 fused into final.
__device__ float g_A[(size_t)NN * D];
__device__ float g_B[(size_t)NN * D];

// ELL storage: packed (col, val_bits). 300000*32*8B = 76.8 MB (L2-resident)
__device__ int2 g_ell[(size_t)NN * WIDTH];
__device__ int  g_len[NN];

// Spill safety net (degree > WIDTH; expected ~tens of edges)
__device__ int   g_spill_count;
__device__ int   g_srow[MAX_SPILL];
__device__ int   g_scol[MAX_SPILL];
__device__ float g_sval[MAX_SPILL];

// ---------------------------------------------------------------------------
__global__ void init_kernel() {
    int i = blockIdx.x * blockDim.x + threadIdx.x;
    const int n4 = NN / 4;                    // 75000
    if (i < n4)
        reinterpret_cast<int4*>(g_len)[i] = make_int4(0, 0, 0, 0);
    if (i == 0) g_spill_count = 0;
}

// 4 edges per thread, vectorized loads. NNZ divisible by 4.
__global__ void ell_fill_kernel(const int*   __restrict__ erow,
                                const int*   __restrict__ ecol,
                                const float* __restrict__ evals) {
    int t = blockIdx.x * blockDim.x + threadIdx.x;
    int i4 = t * 4;
    if (i4 >= NNZ) return;
    int4   r = *reinterpret_cast<const int4*>(erow + i4);
    int4   c = *reinterpret_cast<const int4*>(ecol + i4);
    float4 v = *reinterpret_cast<const float4*>(evals + i4);
    int    rows[4] = {r.x, r.y, r.z, r.w};
    int    cols[4] = {c.x, c.y, c.z, c.w};
    float  vals[4] = {v.x, v.y, v.z, v.w};
#pragma unroll
    for (int k = 0; k < 4; k++) {
        int pos = atomicAdd(&g_len[rows[k]], 1);
        if (pos < WIDTH) {
            g_ell[(size_t)rows[k] * WIDTH + pos] =
                make_int2(cols[k], __float_as_int(vals[k]));
        } else {
            int s = atomicAdd(&g_spill_count, 1);
            if (s < MAX_SPILL) {
                g_srow[s] = rows[k]; g_scol[s] = cols[k]; g_sval[s] = vals[k];
            }
        }
    }
}

// ---------------------------------------------------------------------------
// stage 0: src = (uemb, iemb), dst = g_A ; stage 1: src = g_A, dst = g_B
__device__ __forceinline__ void stage_ptrs(int stage,
                                           const float* uemb, const float* iemb,
                                           const float*& su, const float*& si,
                                           float*& dst) {
    if (stage == 0) { su = uemb; si = iemb;                        dst = g_A; }
    else            { su = g_A;  si = g_A + (size_t)NUM_USERS * D; dst = g_B; }
}

// Warp computes one output row (single ELL chunk, len <= 32).
// Padding iterations carry c=0, v=0: load row 0 (L1-hot), FMA adds 0.
__device__ __forceinline__ float2 spmm_row_acc(int node, int lane,
                                               const float* __restrict__ su,
                                               const float* __restrict__ si) {
    int n = min(g_len[node], WIDTH);
    int2 ev = make_int2(0, 0);
    if (lane < n)
        ev = __ldcs(g_ell + (size_t)node * WIDTH + lane);  // evict-first stream

    float2 acc = make_float2(0.f, 0.f);
    int n4 = (n + 3) & ~3;
    for (int j = 0; j < n4; j += 4) {
#pragma unroll
        for (int k = 0; k < 4; k++) {
            int   cj = __shfl_sync(0xFFFFFFFFu, ev.x, j + k);
            float vj = __int_as_float(__shfl_sync(0xFFFFFFFFu, ev.y, j + k));
            const float* srow = (cj < NUM_USERS)
                              ? (su + (size_t)cj * D)
                              : (si + (size_t)(cj - NUM_USERS) * D);
            float2 x = *reinterpret_cast<const float2*>(srow + 2 * lane);
            acc.x += vj * x.x;
            acc.y += vj * x.y;
        }
    }
    return acc;
}

// Rare-path: add spill-list contributions for rows with degree > WIDTH.
__device__ __forceinline__ float2 spill_patch(int node, int lane, float2 acc,
                                              const float* __restrict__ su,
                                              const float* __restrict__ si) {
    if (g_len[node] > WIDTH) {                 // ~16 rows in the whole graph
        int cnt = min(g_spill_count, MAX_SPILL);
        for (int s = 0; s < cnt; s++) {
            if (g_srow[s] == node) {
                int   cj = g_scol[s];
                float vj = g_sval[s];
                const float* srow = (cj < NUM_USERS)
                                  ? (su + (size_t)cj * D)
                                  : (si + (size_t)(cj - NUM_USERS) * D);
                float2 x = *reinterpret_cast<const float2*>(srow + 2 * lane);
                acc.x += vj * x.x;
                acc.y += vj * x.y;
            }
        }
    }
    return acc;
}

// Full SpMM (layers 1, 2): one warp per destination row, streaming store.
__global__ void spmm_ell_kernel(const float* __restrict__ uemb,
                                const float* __restrict__ iemb,
                                int stage) {
    int warp = (blockIdx.x * blockDim.x + threadIdx.x) >> 5;
    int lane = threadIdx.x & 31;
    if (warp >= NN) return;
    const float* su; const float* si; float* dst;
    stage_ptrs(stage, uemb, iemb, su, si, dst);
    float2 acc = spmm_row_acc(warp, lane, su, si);
    __stcs(reinterpret_cast<float2*>(dst + (size_t)warp * D + 2 * lane), acc);
}

// Spill mop-up for full layers 0,1 (vector atomics; tiny grid, usually no-op).
__global__ void spill_kernel(const float* __restrict__ uemb,
                             const float* __restrict__ iemb,
                             int stage) {
    int cnt = min(g_spill_count, MAX_SPILL);
    int idx = blockIdx.x * blockDim.x + threadIdx.x;
    int e = idx >> 4;
    int q = idx & 15;
    if (e >= cnt) return;

    const float* su; const float* si; float* dst;
    stage_ptrs(stage, uemb, iemb, su, si, dst);

    int   row = g_srow[e];
    int   col = g_scol[e];
    float v   = g_sval[e];
    const float* srow = (col < NUM_USERS)
                      ? (su + (size_t)col * D)
                      : (si + (size_t)(col - NUM_USERS) * D);
    float4 x = *reinterpret_cast<const float4*>(srow + q * 4);
    float* p = dst + (size_t)row * D + q * 4;
    asm volatile("red.global.add.v4.f32 [%0], {%1, %2, %3, %4};"
                 :: "l"(p), "f"(v * x.x), "f"(v * x.y), "f"(v * x.z), "f"(v * x.w)
                 : "memory");
}

// ---------------------------------------------------------------------------
// Fused layer-3 + dot: one warp per pair. e3 rows computed inline from g_B.
// gamma[b] = dot( (e0_u+e1_u+e2_u+e3_u)/4 , (e0_i+e1_i+e2_i+e3_i)/4 )
__global__ void final_kernel(const int*   __restrict__ users,
                             const int*   __restrict__ items,
                             const float* __restrict__ uemb,
                             const float* __restrict__ iemb,
                             float*       __restrict__ out) {
    int warp = (blockIdx.x * blockDim.x + threadIdx.x) >> 5;
    int lane = threadIdx.x & 31;
    if (warp >= BATCH) return;

    int u  = __ldg(users + warp);
    int it = __ldg(items + warp);
    int nu = u;
    int ni = NUM_USERS + it;

    const float* bu = g_B;
    const float* bi = g_B + (size_t)NUM_USERS * D;

    // e3 at the two endpoints (layer-3 SpMM, inline)
    float2 e3u = spmm_row_acc(nu, lane, bu, bi);
    e3u = spill_patch(nu, lane, e3u, bu, bi);
    float2 e3i = spmm_row_acc(ni, lane, bu, bi);
    e3i = spill_patch(ni, lane, e3i, bu, bi);

    size_t urow = (size_t)nu * D + 2 * lane;
    size_t irow = (size_t)ni * D + 2 * lane;

    float2 a_u = *reinterpret_cast<const float2*>(g_A + urow);
    float2 b_u = *reinterpret_cast<const float2*>(g_B + urow);
    float2 e0u = *reinterpret_cast<const float2*>(uemb + (size_t)u * D + 2 * lane);
    float2 a_i = *reinterpret_cast<const float2*>(g_A + irow);
    float2 b_i = *reinterpret_cast<const float2*>(g_B + irow);
    float2 e0i = *reinterpret_cast<const float2*>(iemb + (size_t)it * D + 2 * lane);

    float uvx = e0u.x + a_u.x + b_u.x + e3u.x;
    float uvy = e0u.y + a_u.y + b_u.y + e3u.y;
    float ivx = e0i.x + a_i.x + b_i.x + e3i.x;
    float ivy = e0i.y + a_i.y + b_i.y + e3i.y;

    float dot = uvx * ivx + uvy * ivy;
#pragma unroll
    for (int off = 16; off > 0; off >>= 1)
        dot += __shfl_xor_sync(0xFFFFFFFFu, dot, off);

    if (lane == 0) out[warp] = dot * 0.0625f;   // (1/4)*(1/4)
}

// ---------------------------------------------------------------------------
extern "C" void kernel_launch(void* const* d_in, const int* in_sizes, int n_in,
                              void* d_out, int out_size) {
    const int*   users = (const int*)  d_in[0];
    const int*   items = (const int*)  d_in[1];
    const int*   erow  = (const int*)  d_in[2];
    const int*   ecol  = (const int*)  d_in[3];
    const float* evals = (const float*)d_in[4];
    const float* uemb  = (const float*)d_in[5];
    const float* iemb  = (const float*)d_in[6];
    float* out = (float*)d_out;

    // --- build ELL ---
    init_kernel<<<(NN / 4 + 255) / 256, 256>>>();
    ell_fill_kernel<<<(NNZ / 4 + 255) / 256, 256>>>(erow, ecol, evals);

    int threads = 256;                         // 8 warps/block
    int blocks  = (NN + 7) / 8;                // 37500
    int sblocks = (MAX_SPILL * 16) / 256;      // 128

    // --- layers 1,2 full; layer 3 fused into final ---
    spmm_ell_kernel<<<blocks, threads>>>(uemb, iemb, 0);
    spill_kernel<<<sblocks, 256>>>(uemb, iemb, 0);

    spmm_ell_kernel<<<blocks, threads>>>(uemb, iemb, 1);
    spill_kernel<<<sblocks, 256>>>(uemb, iemb, 1);

    // --- fused layer-3 + gather + dot ---
    final_kernel<<<(BATCH + 7) / 8, 256>>>(users, items, uemb, iemb, out);
}